// round 2
// baseline (speedup 1.0000x reference)
#include <cuda_runtime.h>
#include <math.h>

#define BB 512
#define TT 64
#define NINx 63
#define HH 128

// ------------------------- device scratch (static) -------------------------
__device__ float g_attn[BB * 64];
__device__ float g_gin[(size_t)BB * TT * 512];   // permuted gate order, biases folded
__device__ float g_enc[(size_t)BB * TT * HH];    // input_encoded
__device__ float g_eproj[(size_t)BB * TT * HH];  // enc_proj (+dec_b1)
__device__ float g_hA[BB * HH], g_hB[BB * HH], g_c[BB * HH];
__device__ float g_dhA[BB * HH], g_dhB[BB * HH], g_dc[BB * HH];
__device__ float g_u[BB * HH];
__device__ float g_ctx[BB * HH];
__device__ float g_yt[BB];

__device__ __forceinline__ float sigf(float v) { return 1.0f / (1.0f + expf(-v)); }
__device__ __forceinline__ float tanh_fast(float v) {
    float r; asm("tanh.approx.f32 %0, %1;" : "=f"(r) : "f"(v)); return r;
}

// ------------------------- init states -------------------------
__global__ void zero_state() {
    int i = blockIdx.x * blockDim.x + threadIdx.x;  // 65536 = BB*HH
    g_hA[i] = 0.f; g_c[i] = 0.f; g_dhA[i] = 0.f; g_dc[i] = 0.f;
}

// ------------------------- encoder attention (time-invariant) -------------------------
__global__ void prep_attn(const float* __restrict__ x,
                          const float* __restrict__ attnW,
                          const float* __restrict__ attnB) {
    __shared__ float s_s[64];
    __shared__ float red[2];
    int b = blockIdx.x, n = threadIdx.x;
    float s = -1e30f;
    if (n < NINx) {
        float acc = attnB[0];
        const float* wt = attnW + 2 * HH;
        #pragma unroll 8
        for (int t = 0; t < TT; t++) acc = fmaf(x[b * 4096 + t * 64 + n + 1], wt[t], acc);
        s = acc;
    }
    s_s[n] = s;
    __syncthreads();
    if (n < 32) {
        float m = fmaxf(s_s[n], s_s[n + 32]);
        #pragma unroll
        for (int o = 16; o; o >>= 1) m = fmaxf(m, __shfl_xor_sync(0xffffffffu, m, o));
        if (n == 0) red[0] = m;
    }
    __syncthreads();
    float e = (n < NINx) ? expf(s - red[0]) : 0.f;
    s_s[n] = e;
    __syncthreads();
    if (n < 32) {
        float sm = s_s[n] + s_s[n + 32];
        #pragma unroll
        for (int o = 16; o; o >>= 1) sm += __shfl_xor_sync(0xffffffffu, sm, o);
        if (n == 0) red[1] = sm;
    }
    __syncthreads();
    if (n < 64) g_attn[b * 64 + n] = (n < NINx) ? e / red[1] : 0.f;
}

// ------------- gin[b,t,g'] = sum_n attn[b,n]*x[b,t,n+1]*Wih[orig(g'),n] + bias -------------
__global__ __launch_bounds__(256) void gin_gemm(const float* __restrict__ x,
                                                const float* __restrict__ Wih,
                                                const float* __restrict__ bih,
                                                const float* __restrict__ bhh) {
    __shared__ float attn_s[64];
    __shared__ float As[64][68];
    __shared__ float Ws[64][68];
    int bb = blockIdx.x;
    int g0 = blockIdx.y * 64;
    int tid = threadIdx.x;
    if (tid < 64) attn_s[tid] = g_attn[bb * 64 + tid];
    __syncthreads();
    #pragma unroll
    for (int i = 0; i < 16; i++) {
        int idx = tid + i * 256;
        int m = idx >> 6, k = idx & 63;
        As[k][m] = (k < NINx) ? attn_s[k] * x[bb * 4096 + m * 64 + k + 1] : 0.f;
        int gp = g0 + m;
        int orig = (gp & 3) * HH + (gp >> 2);
        Ws[k][m] = (k < NINx) ? Wih[orig * NINx + k] : 0.f;
    }
    __syncthreads();
    int tx = tid & 15, ty = tid >> 4;
    float acc[4][4];
    #pragma unroll
    for (int i = 0; i < 4; i++)
        #pragma unroll
        for (int j = 0; j < 4; j++) acc[i][j] = 0.f;
    #pragma unroll 4
    for (int k = 0; k < 64; k++) {
        float4 a = *reinterpret_cast<const float4*>(&As[k][ty * 4]);
        float4 w = *reinterpret_cast<const float4*>(&Ws[k][tx * 4]);
        float av[4] = {a.x, a.y, a.z, a.w};
        float wv[4] = {w.x, w.y, w.z, w.w};
        #pragma unroll
        for (int i = 0; i < 4; i++)
            #pragma unroll
            for (int j = 0; j < 4; j++) acc[i][j] = fmaf(av[i], wv[j], acc[i][j]);
    }
    #pragma unroll
    for (int i = 0; i < 4; i++) {
        int t = ty * 4 + i;
        #pragma unroll
        for (int j = 0; j < 4; j++) {
            int gp = g0 + tx * 4 + j;
            int orig = (gp & 3) * HH + (gp >> 2);
            g_gin[((size_t)bb * TT + t) * 512 + gp] = acc[i][j] + bih[orig] + bhh[orig];
        }
    }
}

// ------------------------- fused LSTM step (enc & dec) -------------------------
// grid (16 batch-tiles of 32, 8 unit-tiles of 16), 256 threads
__global__ __launch_bounds__(256) void lstm_step(const float* __restrict__ Whh,
                                                 const float* __restrict__ dWih,
                                                 const float* __restrict__ dbih,
                                                 const float* __restrict__ dbhh,
                                                 int t, int dec) {
    __shared__ float As[128][34];  // h, transposed
    __shared__ float Ws[64][68];   // Whh chunk, transposed, permuted rows
    const float* h_in; float* h_out; float* c;
    if (dec) { h_in = (t & 1) ? g_dhB : g_dhA; h_out = (t & 1) ? g_dhA : g_dhB; c = g_dc; }
    else     { h_in = (t & 1) ? g_hB  : g_hA;  h_out = (t & 1) ? g_hA  : g_hB;  c = g_c;  }
    int b0 = blockIdx.x * 32;
    int g0 = blockIdx.y * 64;
    int tid = threadIdx.x;
    #pragma unroll
    for (int i = 0; i < 16; i++) {
        int idx = tid + i * 256;
        int m = idx >> 7, k = idx & 127;
        As[k][m] = h_in[(b0 + m) * HH + k];
    }
    int tx = tid & 15, ty = tid >> 4;  // cols tx*4 (one unit's i,f,g,o), rows ty*2..+1
    float acc[2][4];
    #pragma unroll
    for (int r = 0; r < 2; r++)
        #pragma unroll
        for (int j = 0; j < 4; j++) acc[r][j] = 0.f;
    for (int kc = 0; kc < 2; kc++) {
        __syncthreads();
        #pragma unroll
        for (int i = 0; i < 16; i++) {
            int idx = tid + i * 256;
            int j = idx >> 6, k = idx & 63;
            int gp = g0 + j;
            int orig = (gp & 3) * HH + (gp >> 2);
            Ws[k][j] = Whh[orig * HH + kc * 64 + k];
        }
        __syncthreads();
        #pragma unroll 4
        for (int k = 0; k < 64; k++) {
            float2 a = *reinterpret_cast<const float2*>(&As[kc * 64 + k][ty * 2]);
            float4 w = *reinterpret_cast<const float4*>(&Ws[k][tx * 4]);
            acc[0][0] = fmaf(a.x, w.x, acc[0][0]);
            acc[0][1] = fmaf(a.x, w.y, acc[0][1]);
            acc[0][2] = fmaf(a.x, w.z, acc[0][2]);
            acc[0][3] = fmaf(a.x, w.w, acc[0][3]);
            acc[1][0] = fmaf(a.y, w.x, acc[1][0]);
            acc[1][1] = fmaf(a.y, w.y, acc[1][1]);
            acc[1][2] = fmaf(a.y, w.z, acc[1][2]);
            acc[1][3] = fmaf(a.y, w.w, acc[1][3]);
        }
    }
    int unit = (g0 >> 2) + tx;
    #pragma unroll
    for (int r = 0; r < 2; r++) {
        int b = b0 + ty * 2 + r;
        float gi, gf, gg, go;
        if (!dec) {
            const float* gp = g_gin + ((size_t)b * TT + t) * 512 + g0 + tx * 4;
            gi = acc[r][0] + gp[0];
            gf = acc[r][1] + gp[1];
            gg = acc[r][2] + gp[2];
            go = acc[r][3] + gp[3];
        } else {
            float y = g_yt[b];
            gi = acc[r][0] + y * dWih[unit]          + dbih[unit]          + dbhh[unit];
            gf = acc[r][1] + y * dWih[HH + unit]     + dbih[HH + unit]     + dbhh[HH + unit];
            gg = acc[r][2] + y * dWih[2 * HH + unit] + dbih[2 * HH + unit] + dbhh[2 * HH + unit];
            go = acc[r][3] + y * dWih[3 * HH + unit] + dbih[3 * HH + unit] + dbhh[3 * HH + unit];
        }
        float cv = sigf(gf) * c[b * HH + unit] + sigf(gi) * tanhf(gg);
        float hv = sigf(go) * tanhf(cv);
        c[b * HH + unit] = cv;
        h_out[b * HH + unit] = hv;
        if (!dec) g_enc[((size_t)b * TT + t) * HH + unit] = hv;
    }
}

// ------------------ enc_proj = input_encoded @ W1e^T + dec_b1 ------------------
__global__ __launch_bounds__(256) void eproj_gemm(const float* __restrict__ W1,
                                                  const float* __restrict__ b1) {
    __shared__ float As[64][68];
    __shared__ float Ws[64][68];
    int m0 = blockIdx.x * 64;
    int n0 = blockIdx.y * 64;
    int tid = threadIdx.x;
    int tx = tid & 15, ty = tid >> 4;
    float acc[4][4];
    #pragma unroll
    for (int i = 0; i < 4; i++)
        #pragma unroll
        for (int j = 0; j < 4; j++) acc[i][j] = 0.f;
    for (int kc = 0; kc < 2; kc++) {
        __syncthreads();
        #pragma unroll
        for (int i = 0; i < 16; i++) {
            int idx = tid + i * 256;
            int m = idx >> 6, k = idx & 63;
            As[k][m] = g_enc[(size_t)(m0 + m) * HH + kc * 64 + k];
            Ws[k][m] = W1[(n0 + m) * 384 + 256 + kc * 64 + k];
        }
        __syncthreads();
        #pragma unroll 4
        for (int k = 0; k < 64; k++) {
            float4 a = *reinterpret_cast<const float4*>(&As[k][ty * 4]);
            float4 w = *reinterpret_cast<const float4*>(&Ws[k][tx * 4]);
            float av[4] = {a.x, a.y, a.z, a.w};
            float wv[4] = {w.x, w.y, w.z, w.w};
            #pragma unroll
            for (int i = 0; i < 4; i++)
                #pragma unroll
                for (int j = 0; j < 4; j++) acc[i][j] = fmaf(av[i], wv[j], acc[i][j]);
        }
    }
    #pragma unroll
    for (int i = 0; i < 4; i++) {
        int row = m0 + ty * 4 + i;
        #pragma unroll
        for (int j = 0; j < 4; j++) {
            int n = n0 + tx * 4 + j;
            g_eproj[(size_t)row * HH + n] = acc[i][j] + b1[n];
        }
    }
}

// ------------------ decoder: u = h @ W1h^T + c @ W1c^T ------------------
__global__ __launch_bounds__(256) void dec_proj(const float* __restrict__ W1, int t) {
    __shared__ float hc[16][256];
    __shared__ float W1s[64][66];
    const float* h_in = (t & 1) ? g_dhB : g_dhA;
    int b0 = blockIdx.x * 16, e0 = blockIdx.y * 64, tid = threadIdx.x;
    #pragma unroll
    for (int i = 0; i < 16; i++) {
        int idx = tid + i * 256;
        int m = idx >> 8, k = idx & 255;
        hc[m][k] = (k < 128) ? h_in[(b0 + m) * HH + k] : g_dc[(b0 + m) * HH + (k - 128)];
    }
    int tx = tid & 31, grp = tid >> 5;  // e = e0+tx*2..+1, batches grp*2..+1
    float acc[2][2];
    acc[0][0] = acc[0][1] = acc[1][0] = acc[1][1] = 0.f;
    for (int kc = 0; kc < 4; kc++) {
        __syncthreads();
        #pragma unroll
        for (int i = 0; i < 16; i++) {
            int idx = tid + i * 256;
            int e = idx >> 6, k = idx & 63;
            W1s[k][e] = W1[(e0 + e) * 384 + kc * 64 + k];
        }
        __syncthreads();
        #pragma unroll 4
        for (int k = 0; k < 64; k++) {
            float2 w = *reinterpret_cast<const float2*>(&W1s[k][tx * 2]);
            float h0 = hc[grp * 2][kc * 64 + k];
            float h1 = hc[grp * 2 + 1][kc * 64 + k];
            acc[0][0] = fmaf(w.x, h0, acc[0][0]);
            acc[0][1] = fmaf(w.y, h0, acc[0][1]);
            acc[1][0] = fmaf(w.x, h1, acc[1][0]);
            acc[1][1] = fmaf(w.y, h1, acc[1][1]);
        }
    }
    #pragma unroll
    for (int r = 0; r < 2; r++) {
        int b = b0 + grp * 2 + r;
        g_u[b * HH + e0 + tx * 2]     = acc[r][0];
        g_u[b * HH + e0 + tx * 2 + 1] = acc[r][1];
    }
}

// ---------- decoder attention + context + y_tilde (fused, per-batch block) ----------
__global__ __launch_bounds__(256) void dec_attn(const float* __restrict__ W2,
                                                const float* __restrict__ fcW,
                                                const float* __restrict__ fcb,
                                                const float* __restrict__ x, int t) {
    __shared__ float u_s[128];
    __shared__ float sc[64];
    __shared__ float red[8];
    int b = blockIdx.x, tid = threadIdx.x, lane = tid & 31, w = tid >> 5;
    if (tid < 128) u_s[tid] = g_u[b * HH + tid];
    __syncthreads();
    const float* ep = g_eproj + (size_t)b * TT * HH;
    #pragma unroll
    for (int i = 0; i < 8; i++) {
        int tt = w * 8 + i;
        float p = 0.f;
        #pragma unroll
        for (int q = 0; q < 4; q++) {
            int e = lane + q * 32;
            p = fmaf(W2[e], tanh_fast(ep[tt * HH + e] + u_s[e]), p);
        }
        #pragma unroll
        for (int o = 16; o; o >>= 1) p += __shfl_xor_sync(0xffffffffu, p, o);
        if (lane == 0) sc[tt] = p;
    }
    __syncthreads();
    if (w == 0) {
        float s0 = sc[lane], s1 = sc[lane + 32];
        float m = fmaxf(s0, s1);
        #pragma unroll
        for (int o = 16; o; o >>= 1) m = fmaxf(m, __shfl_xor_sync(0xffffffffu, m, o));
        float e0 = expf(s0 - m), e1 = expf(s1 - m);
        float sm = e0 + e1;
        #pragma unroll
        for (int o = 16; o; o >>= 1) sm += __shfl_xor_sync(0xffffffffu, sm, o);
        sc[lane] = e0 / sm;
        sc[lane + 32] = e1 / sm;
    }
    __syncthreads();
    float yp = 0.f;
    if (tid < 128) {
        const float* en = g_enc + (size_t)b * TT * HH;
        float a = 0.f;
        #pragma unroll 8
        for (int tt = 0; tt < 64; tt++) a = fmaf(sc[tt], en[tt * HH + tid], a);
        g_ctx[b * HH + tid] = a;
        yp = a * fcW[tid];
    }
    #pragma unroll
    for (int o = 16; o; o >>= 1) yp += __shfl_xor_sync(0xffffffffu, yp, o);
    if (lane == 0) red[w] = yp;
    __syncthreads();
    if (tid == 0)
        g_yt[b] = red[0] + red[1] + red[2] + red[3]
                + x[b * 4096 + t * 64] * fcW[128] + fcb[0];
}

// ------------------------- final FC -------------------------
__global__ __launch_bounds__(128) void final_fc(const float* __restrict__ fcfW,
                                                const float* __restrict__ fcfb,
                                                float* __restrict__ out) {
    __shared__ float red[4];
    int b = blockIdx.x, tid = threadIdx.x;
    float p = g_dhA[b * HH + tid] * fcfW[tid] + g_ctx[b * HH + tid] * fcfW[128 + tid];
    #pragma unroll
    for (int o = 16; o; o >>= 1) p += __shfl_xor_sync(0xffffffffu, p, o);
    if ((tid & 31) == 0) red[tid >> 5] = p;
    __syncthreads();
    if (tid == 0) out[b] = red[0] + red[1] + red[2] + red[3] + fcfb[0];
}

// ------------------------- launch -------------------------
extern "C" void kernel_launch(void* const* d_in, const int* in_sizes, int n_in,
                              void* d_out, int out_size) {
    const float* x        = (const float*)d_in[0];
    const float* attnW    = (const float*)d_in[1];
    const float* attnB    = (const float*)d_in[2];
    const float* enc_Wih  = (const float*)d_in[3];
    const float* enc_Whh  = (const float*)d_in[4];
    const float* enc_bih  = (const float*)d_in[5];
    const float* enc_bhh  = (const float*)d_in[6];
    const float* dec_W1   = (const float*)d_in[7];
    const float* dec_b1   = (const float*)d_in[8];
    const float* dec_W2   = (const float*)d_in[9];
    // d_in[10] = dec_b2 (cancels in softmax)
    const float* dec_Wih  = (const float*)d_in[11];
    const float* dec_Whh  = (const float*)d_in[12];
    const float* dec_bih  = (const float*)d_in[13];
    const float* dec_bhh  = (const float*)d_in[14];
    const float* fc_W     = (const float*)d_in[15];
    const float* fc_b     = (const float*)d_in[16];
    const float* fcf_W    = (const float*)d_in[17];
    const float* fcf_b    = (const float*)d_in[18];
    float* out = (float*)d_out;

    zero_state<<<256, 256>>>();
    prep_attn<<<BB, 64>>>(x, attnW, attnB);
    gin_gemm<<<dim3(BB, 8), 256>>>(x, enc_Wih, enc_bih, enc_bhh);
    for (int t = 0; t < TT; t++)
        lstm_step<<<dim3(16, 8), 256>>>(enc_Whh, nullptr, nullptr, nullptr, t, 0);
    eproj_gemm<<<dim3(512, 2), 256>>>(dec_W1, dec_b1);
    for (int t = 0; t < TT; t++) {
        dec_proj<<<dim3(32, 2), 256>>>(dec_W1, t);
        dec_attn<<<BB, 256>>>(dec_W2, fc_W, fc_b, x, t);
        lstm_step<<<dim3(16, 8), 256>>>(dec_Whh, dec_Wih, dec_bih, dec_bhh, t, 1);
    }
    final_fc<<<BB, 128>>>(fcf_W, fcf_b, out);
}